// round 2
// baseline (speedup 1.0000x reference)
#include <cuda_runtime.h>
#include <math.h>
#include <stdint.h>

#define NPTS (32*64*64)   // 131072
#define D 64
#define KC 512
#define MB 128            // points per k1 block
#define BIAS 512.0f
#define GAP_TH 0.10f

// ---------------- scratch (device globals; no allocations allowed) ----------------
__device__ int   g_idx[NPTS];
__device__ int   g_order[NPTS];
__device__ int   g_icounts[KC];
__device__ int   g_start[KC];
__device__ int   g_cursor[KC];
__device__ float g_embedsumT[D*KC];  // [d][k]
__device__ float g_sm[KC];
__device__ float g_losssum;

// f32x2 packed FMA: dst = a*b + c (elementwise on packed f32 pairs)
#define FMA2(dst, a, b, c) asm("fma.rn.f32x2 %0, %1, %2, %3;" : "=l"(dst) : "l"(a), "l"(b), "l"(c))
#define PACK2(dst, f)      asm("mov.b64 %0, {%1, %1};" : "=l"(dst) : "f"(f))
#define UNPK2(lo, hi, v)   asm("mov.b64 {%0, %1}, %2;" : "=f"(lo), "=f"(hi) : "l"(v))

__device__ __forceinline__ void lds128_u64(unsigned addr, unsigned long long& a, unsigned long long& b) {
    asm volatile("ld.shared.v2.u64 {%0, %1}, [%2];" : "=l"(a), "=l"(b) : "r"(addr));
}

// top-4 running-min insert on ordered uints
__device__ __forceinline__ void ins4(unsigned u, unsigned& b1, unsigned& b2, unsigned& b3, unsigned& b4) {
    unsigned t1 = max(b1, u); b1 = min(b1, u);
    unsigned t2 = max(b2, t1); b2 = min(b2, t1);
    unsigned t3 = max(b3, t2); b3 = min(b3, t2);
    b4 = min(b4, t3);
}

// ---------------- K0: zero per-replay scratch ----------------
__global__ void k0_zero() {
    int i = blockIdx.x*blockDim.x + threadIdx.x;
    if (i < KC) g_icounts[i] = 0;
    if (i == 0) g_losssum = 0.f;
}

// ---------------- K1 ----------------
// smem layout (in floats)
#define SE_OFF   0                   // E [d][k]: 64*512 = 32768
#define ZT_OFF   32768               // zT [d][p]: 64*128 = 8192
#define E2_OFF   (32768+8192)        // e2+bias: 512
#define SB_OFF   (E2_OFF+512)        // best cand: 8 tx * 128 p * 4 uint = 4096
#define SH_OFF   (SB_OFF+4096)       // hist: 512
#define SR_OFF   (SH_OFF+512)        // loss warp partials: 4
#define SMEM_F   (SR_OFF+8)
#define SMEM_B   (SMEM_F*4)

__global__ void __launch_bounds__(256) k1_main(
    const float* __restrict__ z, const float* __restrict__ E, float* __restrict__ outq)
{
    extern __shared__ float sm[];
    float* sE  = sm + SE_OFF;     // [d][k]
    float* zT  = sm + ZT_OFF;     // [d][p]
    float* e2b = sm + E2_OFF;
    unsigned* sBest = (unsigned*)(sm + SB_OFF);
    int*   sHist = (int*)(sm + SH_OFF);
    float* sRed  = sm + SR_OFF;

    const int tid = threadIdx.x;
    const int tx  = tid & 7;       // code slice
    const int ty  = tid >> 3;      // point group (4 points)
    const int gbase = blockIdx.x * MB;

    // E copy (same [d][k] layout, coalesced)
    {
        const float4* Ev = (const float4*)E;
        float4* sEv = (float4*)sE;
        #pragma unroll
        for (int j = 0; j < 32; j++) sEv[tid + j*256] = Ev[tid + j*256];
    }
    // z tile -> zT[d][p]
    {
        const float4* zv = (const float4*)(z + (size_t)gbase*D);
        #pragma unroll
        for (int j = 0; j < 8; j++) {
            int e4 = tid*8 + j;
            int p = e4 >> 4, dg = (e4 & 15) * 4;
            float4 v = zv[e4];
            zT[(dg+0)*MB + p] = v.x;
            zT[(dg+1)*MB + p] = v.y;
            zT[(dg+2)*MB + p] = v.z;
            zT[(dg+3)*MB + p] = v.w;
        }
    }
    for (int i = tid; i < KC; i += 256) sHist[i] = 0;
    __syncthreads();

    for (int k = tid; k < KC; k += 256) {
        float s = BIAS;
        #pragma unroll 16
        for (int d = 0; d < D; d++) { float e = sE[d*KC + k]; s = fmaf(e, e, s); }
        e2b[k] = s;
    }
    __syncthreads();

    const unsigned sE_sh = (unsigned)__cvta_generic_to_shared(sE);

    unsigned b1[4], b2[4], b3[4], b4[4];
    #pragma unroll
    for (int i = 0; i < 4; i++) { b1[i]=b2[i]=b3[i]=b4[i]=0xFFFFFFFFu; }

    for (int s = 0; s < 2; s++) {
        const int cb = s*256;
        // acc[q][i][h]: q=0..7 code-quad groups, i=0..3 points, h=0..1 code-pair halves
        unsigned long long acc[64];
        #pragma unroll
        for (int j = 0; j < 64; j++) acc[j] = 0ULL;

        const unsigned eBase = sE_sh + (unsigned)(cb + tx*4)*4u;

        #pragma unroll 8
        for (int d = 0; d < D; d++) {
            float4 zv = *(const float4*)(zT + d*MB + ty*4);
            unsigned long long zz0, zz1, zz2, zz3;
            PACK2(zz0, zv.x); PACK2(zz1, zv.y); PACK2(zz2, zv.z); PACK2(zz3, zv.w);
            const unsigned eRow = eBase + (unsigned)d*2048u;
            #pragma unroll
            for (int q = 0; q < 8; q++) {
                unsigned long long e0, e1;   // e0 = codes (c,c+1), e1 = codes (c+2,c+3)
                lds128_u64(eRow + (unsigned)q*128u, e0, e1);
                unsigned long long* a = acc + q*8;
                FMA2(a[0], e0, zz0, a[0]);  FMA2(a[1], e1, zz0, a[1]);
                FMA2(a[2], e0, zz1, a[2]);  FMA2(a[3], e1, zz1, a[3]);
                FMA2(a[4], e0, zz2, a[4]);  FMA2(a[5], e1, zz2, a[5]);
                FMA2(a[6], e0, zz3, a[6]);  FMA2(a[7], e1, zz3, a[7]);
            }
        }

        // epilogue: scores -> packed top-4 per point
        #pragma unroll
        for (int q = 0; q < 8; q++) {
            const int cbase = cb + q*32 + tx*4;
            float4 eb = *(const float4*)(e2b + cbase);
            #pragma unroll
            for (int i = 0; i < 4; i++) {
                const unsigned long long* a = acc + q*8 + i*2;
                float d0, d1, d2, d3;
                UNPK2(d0, d1, a[0]);   // codes cbase+0, cbase+1
                UNPK2(d2, d3, a[1]);   // codes cbase+2, cbase+3
                float s0 = fmaf(-2.f, d0, eb.x);
                float s1 = fmaf(-2.f, d1, eb.y);
                float s2 = fmaf(-2.f, d2, eb.z);
                float s3 = fmaf(-2.f, d3, eb.w);
                unsigned u0 = (__float_as_uint(s0) & 0xFFFFFE00u) | (unsigned)(cbase+0);
                unsigned u1 = (__float_as_uint(s1) & 0xFFFFFE00u) | (unsigned)(cbase+1);
                unsigned u2 = (__float_as_uint(s2) & 0xFFFFFE00u) | (unsigned)(cbase+2);
                unsigned u3 = (__float_as_uint(s3) & 0xFFFFFE00u) | (unsigned)(cbase+3);
                ins4(u0, b1[i], b2[i], b3[i], b4[i]);
                ins4(u1, b1[i], b2[i], b3[i], b4[i]);
                ins4(u2, b1[i], b2[i], b3[i], b4[i]);
                ins4(u3, b1[i], b2[i], b3[i], b4[i]);
            }
        }
    }

    // publish per-(tx,point) top-4
    #pragma unroll
    for (int i = 0; i < 4; i++) {
        unsigned* dst = sBest + ((ty*4 + i)*8 + tx)*4;
        dst[0] = b1[i]; dst[1] = b2[i]; dst[2] = b3[i]; dst[3] = b4[i];
    }
    __syncthreads();

    // final per-point: combine 8 tx slices, refine, outputs
    float lossLocal = 0.f;
    if (tid < MB) {
        const int p = tid;
        unsigned c1=0xFFFFFFFFu, c2=0xFFFFFFFFu, c3=0xFFFFFFFFu, c4=0xFFFFFFFFu;
        const unsigned* src = sBest + p*8*4;
        #pragma unroll
        for (int j = 0; j < 32; j++) ins4(src[j], c1, c2, c3, c4);

        float s1f = __uint_as_float(c1 & 0xFFFFFE00u);
        float s2f = __uint_as_float(c2 & 0xFFFFFE00u);
        float s3f = __uint_as_float(c3 & 0xFFFFFE00u);
        float s4f = __uint_as_float(c4 & 0xFFFFFE00u);
        int id = (int)(c1 & 0x1FFu);

        if (s2f - s1f < GAP_TH) {
            int cand[4]; int nc = 2;
            cand[0] = id; cand[1] = (int)(c2 & 0x1FFu);
            if (s3f - s1f < GAP_TH) cand[nc++] = (int)(c3 & 0x1FFu);
            if (s4f - s1f < GAP_TH) cand[nc++] = (int)(c4 & 0x1FFu);
            double bestd = 1e300; int bestk = id;
            for (int c = 0; c < nc; c++) {
                const int k = cand[c];
                double dd = 0.0;
                #pragma unroll 8
                for (int d = 0; d < D; d++) {
                    double t = (double)zT[d*MB + p] - (double)sE[d*KC + k];
                    dd += t*t;
                }
                if (dd < bestd || (dd == bestd && k < bestk)) { bestd = dd; bestk = k; }
            }
            id = bestk;
        }

        g_idx[gbase + p] = id;
        atomicAdd(&sHist[id], 1);

        // quantized row + loss
        float4 qv[16];
        #pragma unroll
        for (int j = 0; j < 16; j++) {
            float e0 = sE[(4*j+0)*KC + id], e1 = sE[(4*j+1)*KC + id];
            float e2v = sE[(4*j+2)*KC + id], e3 = sE[(4*j+3)*KC + id];
            float z0 = zT[(4*j+0)*MB + p], z1v = zT[(4*j+1)*MB + p];
            float z2 = zT[(4*j+2)*MB + p], z3 = zT[(4*j+3)*MB + p];
            float t0 = e0-z0, t1 = e1-z1v, t2 = e2v-z2, t3 = e3-z3;
            lossLocal = fmaf(t0,t0, fmaf(t1,t1, fmaf(t2,t2, fmaf(t3,t3, lossLocal))));
            qv[j] = make_float4(e0, e1, e2v, e3);
        }
        float4* outp = (float4*)(outq + (size_t)(gbase + p)*D);
        #pragma unroll
        for (int j = 0; j < 16; j++) outp[j] = qv[j];
    }

    // loss reduce (threads 0..127 hold values; others contribute 0)
    float v = (tid < MB) ? lossLocal : 0.f;
    #pragma unroll
    for (int o = 16; o; o >>= 1) v += __shfl_down_sync(0xffffffffu, v, o);
    if ((tid & 31) == 0 && tid < MB) sRed[tid >> 5] = v;
    __syncthreads();
    if (tid == 0) {
        atomicAdd(&g_losssum, sRed[0] + sRed[1] + sRed[2] + sRed[3]);
    }
    // flush histogram
    for (int i = tid; i < KC; i += 256) {
        int c = sHist[i];
        if (c) atomicAdd(&g_icounts[i], c);
    }
}

// ---------------- K2a: prefix sum over counts ----------------
__global__ void __launch_bounds__(512) k2a_scan() {
    __shared__ int s[KC];
    const int t = threadIdx.x;
    s[t] = g_icounts[t];
    __syncthreads();
    int val = s[t];
    #pragma unroll
    for (int o = 1; o < KC; o <<= 1) {
        int add = (t >= o) ? s[t - o] : 0;
        __syncthreads();
        s[t] = val = val + add;
        __syncthreads();
    }
    int excl = val - g_icounts[t];
    g_start[t] = excl;
    g_cursor[t] = excl;
}

// ---------------- K2b: bucket scatter ----------------
__global__ void __launch_bounds__(256) k2b_scatter() {
    int p = blockIdx.x*256 + threadIdx.x;
    int id = g_idx[p];
    int pos = atomicAdd(&g_cursor[id], 1);
    g_order[pos] = p;
}

// ---------------- K2c: per-code segment sum (no atomics) ----------------
__global__ void __launch_bounds__(64) k2c_sum(const float* __restrict__ z) {
    const int k = blockIdx.x;
    const int d = threadIdx.x;
    const int start = g_start[k];
    const int cnt = g_icounts[k];
    float acc = 0.f;
    int i = 0;
    for (; i + 4 <= cnt; i += 4) {
        int p0 = g_order[start+i],   p1 = g_order[start+i+1];
        int p2 = g_order[start+i+2], p3 = g_order[start+i+3];
        acc += z[(size_t)p0*D + d] + z[(size_t)p1*D + d]
             + z[(size_t)p2*D + d] + z[(size_t)p3*D + d];
    }
    for (; i < cnt; i++) acc += z[(size_t)g_order[start+i]*D + d];
    g_embedsumT[d*KC + k] = acc;
}

// ---------------- K3a: cluster-size EMA, smoothing, loss ----------------
__global__ void __launch_bounds__(512) k3a(const float* __restrict__ cs, float* __restrict__ out) {
    __shared__ float sRed[16];
    __shared__ float sN;
    const int t = threadIdx.x;
    float ncs = cs[t]*0.99f + 0.01f*(float)g_icounts[t];
    out[(size_t)NPTS*D + 1 + KC*D + t] = ncs;   // new_cluster_size

    float v = ncs;
    #pragma unroll
    for (int o = 16; o; o >>= 1) v += __shfl_down_sync(0xffffffffu, v, o);
    if ((t & 31) == 0) sRed[t >> 5] = v;
    __syncthreads();
    if (t < 16) {
        float w = sRed[t];
        #pragma unroll
        for (int o = 8; o; o >>= 1) w += __shfl_down_sync(0xffffu, w, o);
        if (t == 0) sN = w;
    }
    __syncthreads();
    const float n = sN;
    g_sm[t] = (ncs + 1e-5f) / (n + (float)KC * 1e-5f) * n;
    if (t == 0) out[(size_t)NPTS*D] = 0.25f * (g_losssum / (float)((size_t)NPTS * D));
}

// ---------------- K3b: embed_avg EMA + new embedding ----------------
__global__ void __launch_bounds__(512) k3b(const float* __restrict__ ea, float* __restrict__ out) {
    const int d = blockIdx.x;
    const int k = threadIdx.x;
    const int i = d*KC + k;
    float* out_emb = out + (size_t)NPTS*D + 1;
    float* out_nea = out_emb + KC*D + KC;
    float nea = ea[i]*0.99f + 0.01f*g_embedsumT[i];
    out_nea[i] = nea;
    out_emb[i] = nea / g_sm[k];
}

// ---------------- launch ----------------
extern "C" void kernel_launch(void* const* d_in, const int* in_sizes, int n_in,
                              void* d_out, int out_size)
{
    const float* z  = (const float*)d_in[0];
    const float* E  = (const float*)d_in[1];
    const float* cs = (const float*)d_in[2];
    const float* ea = (const float*)d_in[3];
    float* out = (float*)d_out;

    cudaFuncSetAttribute(k1_main, cudaFuncAttributeMaxDynamicSharedMemorySize, SMEM_B);

    k0_zero<<<2, 256>>>();
    k1_main<<<NPTS/MB, 256, SMEM_B>>>(z, E, out);
    k2a_scan<<<1, 512>>>();
    k2b_scatter<<<NPTS/256, 256>>>();
    k2c_sum<<<KC, 64>>>(z);
    k3a<<<1, 512>>>(cs, out);
    k3b<<<D, 512>>>(ea, out);
}

// round 5
// speedup vs baseline: 1.2772x; 1.2772x over previous
#include <cuda_runtime.h>
#include <cuda_bf16.h>
#include <stdint.h>

#define NPTS   131072
#define DDIM   64
#define KC     512
#define MB     128
#define NTILES 1024          // NPTS / MB
#define GRID1  148
#define NTHR   256
#define TH_I   8             // refine threshold in 1/2048 score units (~3.9e-3)

// ---------------- device-global scratch (no allocations allowed) ----------------
__device__ int   g_idx[NPTS];
__device__ int   g_order[NPTS];
__device__ int   g_bh[NTILES*KC];     // per-tile histograms
__device__ int   g_toff[NTILES*KC];   // per-tile exclusive offsets (per code)
__device__ int   g_icounts[KC];
__device__ int   g_start[KC];
__device__ float g_e2pre[KC];         // (||e||^2 + 512) * 2048
__device__ float g_embedsumT[DDIM*KC];
__device__ float g_smooth[KC];
__device__ float g_losssum;

// ---------------- smem layout (float indices); bases 1024B-aligned for SW128 ----
#define B_HI  0        // [512 codes][64 d] bf16 SW128 : 16384 floats (64KB)
#define B_LO  16384
#define A_HI  32768    // [128 pts][64 d] bf16 SW128   : 4096 floats (16KB)
#define A_LO  36864
#define PREB  40960    // 512 floats
#define HISTO 41472    // 512 ints
#define STOP  41984    // 128*3 uints
#define SIDO  42368    // 128 ints
#define SRED  42496    // 8 floats
#define SMEMF 42512
#define SMEMB (SMEMF*4)

#define SW(o) ((o) ^ (((o) >> 3) & 0x70))

static __device__ __forceinline__ uint32_t smem_u32(const void* p) {
    uint32_t a;
    asm("{ .reg .u64 t; cvta.to.shared.u64 t, %1; cvt.u32.u64 %0, t; }" : "=r"(a) : "l"(p));
    return a;
}
static __device__ __forceinline__ void ldsm_x4(uint32_t addr, unsigned* r) {
    asm volatile("ldmatrix.sync.aligned.m8n8.x4.shared.b16 {%0,%1,%2,%3}, [%4];"
        : "=r"(r[0]), "=r"(r[1]), "=r"(r[2]), "=r"(r[3]) : "r"(addr));
}
static __device__ __forceinline__ void mma_bf16(float* c, const unsigned* a, const unsigned* b) {
    asm volatile("mma.sync.aligned.m16n8k16.row.col.f32.bf16.bf16.f32 "
        "{%0,%1,%2,%3}, {%4,%5,%6,%7}, {%8,%9}, {%0,%1,%2,%3};"
        : "+f"(c[0]), "+f"(c[1]), "+f"(c[2]), "+f"(c[3])
        : "r"(a[0]), "r"(a[1]), "r"(a[2]), "r"(a[3]), "r"(b[0]), "r"(b[1]));
}
static __device__ __forceinline__ void ins3(unsigned u, unsigned& b1, unsigned& b2, unsigned& b3) {
    unsigned t1 = umax(b1, u);  b1 = umin(b1, u);
    unsigned t2 = umax(b2, t1); b2 = umin(b2, t1);
    b3 = umin(b3, t2);
}

// ---------------- K0: e2 precompute + loss zero ----------------
__global__ void __launch_bounds__(512) k0_prep(const float* __restrict__ E) {
    int k = threadIdx.x;
    double s = 0.0;
    for (int d = 0; d < DDIM; d++) { float e = E[d*KC + k]; s += (double)e * (double)e; }
    g_e2pre[k] = (float)((s + 512.0) * 2048.0);
    if (k == 0) g_losssum = 0.f;
}

// ---------------- K1: persistent HMMA distance + argmin + quantized + loss + hist ----
__global__ void __launch_bounds__(NTHR, 1) k1_main(
    const float* __restrict__ z, const float* __restrict__ E, float* __restrict__ outq)
{
    extern __shared__ float sm[];
    const int tid = threadIdx.x;
    const int w = tid >> 5, lane = tid & 31;
    const uint32_t sbase = smem_u32(sm);

    float*    pre   = sm + PREB;
    int*      sHist = (int*)(sm + HISTO);
    unsigned* sTop  = (unsigned*)(sm + STOP);
    int*      sId   = (int*)(sm + SIDO);
    float*    sRed  = sm + SRED;

    // one-time: E -> B_hi/B_lo as [code][d] bf16, SW128; load pre
    for (int i = tid; i < DDIM*KC; i += NTHR) {
        int d = i >> 9, k = i & (KC-1);
        float x = E[i];
        __nv_bfloat16 hi = __float2bfloat16_rn(x);
        __nv_bfloat16 lo = __float2bfloat16_rn(x - __bfloat162float(hi));
        unsigned byte = SW((unsigned)(k*128 + d*2));
        *(__nv_bfloat16*)((char*)(sm + B_HI) + byte) = hi;
        *(__nv_bfloat16*)((char*)(sm + B_LO) + byte) = lo;
    }
    for (int i = tid; i < KC; i += NTHR) pre[i] = g_e2pre[i];
    __syncthreads();

    const uint32_t aHiB = sbase + A_HI*4, aLoB = sbase + A_LO*4;
    const uint32_t bHiB = sbase + B_HI*4, bLoB = sbase + B_LO*4;

    // lane-constant fragment address components
    const int mA = lane >> 3, rA = lane & 7;
    const unsigned aLaneOff = (unsigned)(((rA + ((mA & 1) << 3)) * 128) + ((mA >> 1) << 4));
    const unsigned bLaneOff = (unsigned)(((rA + ((mA >> 1) << 3)) * 128) + ((mA & 1) << 4));

    const int p0 = w * 16;   // 16 points per warp
    float ctaLoss = 0.f;

    #pragma unroll 1
    for (int t = blockIdx.x; t < NTILES; t += GRID1) {
        const size_t gbase = (size_t)t * MB;

        // ---- prologue: zero hist; z tile -> A_hi/A_lo (SW128) ----
        for (int i = tid; i < KC; i += NTHR) sHist[i] = 0;
        {
            const float4* zp = (const float4*)(z + gbase*DDIM);
            #pragma unroll
            for (int j = 0; j < 8; j++) {
                int e4 = tid + j*NTHR;            // 0..2047
                int p = e4 >> 4, d0 = (e4 & 15) * 4;
                float4 v = zp[e4];
                float vv[4] = {v.x, v.y, v.z, v.w};
                #pragma unroll
                for (int q = 0; q < 4; q += 2) {
                    __nv_bfloat16 h0 = __float2bfloat16_rn(vv[q]);
                    __nv_bfloat16 l0 = __float2bfloat16_rn(vv[q]   - __bfloat162float(h0));
                    __nv_bfloat16 h1 = __float2bfloat16_rn(vv[q+1]);
                    __nv_bfloat16 l1 = __float2bfloat16_rn(vv[q+1] - __bfloat162float(h1));
                    unsigned byte = SW((unsigned)(p*128 + (d0+q)*2));
                    *(__nv_bfloat162*)((char*)(sm + A_HI) + byte) = __nv_bfloat162(h0, h1);
                    *(__nv_bfloat162*)((char*)(sm + A_LO) + byte) = __nv_bfloat162(l0, l1);
                }
            }
        }
        __syncthreads();

        // ---- A fragments: register-resident for whole tile ----
        unsigned ahi[4][4], alo[4][4];
        #pragma unroll
        for (int ks = 0; ks < 4; ks++) {
            unsigned o = SW((unsigned)(p0*128) + (unsigned)(ks*32) + aLaneOff);
            ldsm_x4(aHiB + o, ahi[ks]);
            ldsm_x4(aLoB + o, alo[ks]);
        }

        // ---- MMA mainloop + epilogue: top-3 over 512 codes, 2 point-rows/thread ----
        unsigned lo1 = 0xFFFFFFFFu, lo2 = 0xFFFFFFFFu, lo3 = 0xFFFFFFFFu;  // point p0+g
        unsigned hi1 = 0xFFFFFFFFu, hi2 = 0xFFFFFFFFu, hi3 = 0xFFFFFFFFu;  // point p0+g+8

        #pragma unroll 1
        for (int chunk = 0; chunk < 8; chunk++) {
            const int cb = chunk * 64;
            float acc[8][4];
            #pragma unroll
            for (int i = 0; i < 8; i++)
                { acc[i][0] = 0.f; acc[i][1] = 0.f; acc[i][2] = 0.f; acc[i][3] = 0.f; }

            #pragma unroll
            for (int ks = 0; ks < 4; ks++) {
                const unsigned kb = (unsigned)(ks*32);
                #pragma unroll
                for (int pr = 0; pr < 4; pr++) {
                    unsigned o = SW((unsigned)((cb + pr*16)*128) + kb + bLaneOff);
                    unsigned bh[4], bl[4];
                    ldsm_x4(bHiB + o, bh);
                    ldsm_x4(bLoB + o, bl);
                    mma_bf16(acc[pr*2],   ahi[ks], bh);
                    mma_bf16(acc[pr*2+1], ahi[ks], bh + 2);
                    mma_bf16(acc[pr*2],   alo[ks], bh);
                    mma_bf16(acc[pr*2+1], alo[ks], bh + 2);
                    mma_bf16(acc[pr*2],   ahi[ks], bl);
                    mma_bf16(acc[pr*2+1], ahi[ks], bl + 2);
                }
            }
            // epilogue: scores -> packed top-3
            #pragma unroll
            for (int tt = 0; tt < 8; tt++) {
                const int code0 = cb + tt*8 + 2*(lane & 3);
                float2 p2 = *(const float2*)(pre + code0);
                float s0 = fmaf(acc[tt][0], -4096.f, p2.x);
                float s1 = fmaf(acc[tt][1], -4096.f, p2.y);
                float s2 = fmaf(acc[tt][2], -4096.f, p2.x);
                float s3 = fmaf(acc[tt][3], -4096.f, p2.y);
                unsigned u0 = (__float2uint_rn(s0) << 9) | (unsigned)code0;
                unsigned u1 = (__float2uint_rn(s1) << 9) | (unsigned)(code0 + 1);
                unsigned u2 = (__float2uint_rn(s2) << 9) | (unsigned)code0;
                unsigned u3 = (__float2uint_rn(s3) << 9) | (unsigned)(code0 + 1);
                ins3(u0, lo1, lo2, lo3);
                ins3(u1, lo1, lo2, lo3);
                ins3(u2, hi1, hi2, hi3);
                ins3(u3, hi1, hi2, hi3);
            }
        }

        // merge across the 4 lanes sharing each point row
        #pragma unroll
        for (int o = 1; o <= 2; o <<= 1) {
            ins3(__shfl_xor_sync(0xffffffffu, lo1, o), lo1, lo2, lo3);
            ins3(__shfl_xor_sync(0xffffffffu, lo2, o), lo1, lo2, lo3);
            ins3(__shfl_xor_sync(0xffffffffu, lo3, o), lo1, lo2, lo3);
            ins3(__shfl_xor_sync(0xffffffffu, hi1, o), hi1, hi2, hi3);
            ins3(__shfl_xor_sync(0xffffffffu, hi2, o), hi1, hi2, hi3);
            ins3(__shfl_xor_sync(0xffffffffu, hi3, o), hi1, hi2, hi3);
        }
        if ((lane & 3) == 0) {
            int pA = p0 + (lane >> 2);
            sTop[pA*3+0] = lo1; sTop[pA*3+1] = lo2; sTop[pA*3+2] = lo3;
            sTop[(pA+8)*3+0] = hi1; sTop[(pA+8)*3+1] = hi2; sTop[(pA+8)*3+2] = hi3;
        }
        __syncthreads();

        // ---- per-point: refine near-ties exactly (gmem z,E in fp64), commit id ----
        if (tid < MB) {
            unsigned m1 = sTop[tid*3], m2 = sTop[tid*3+1], m3 = sTop[tid*3+2];
            int id = (int)(m1 & 511u);
            if ((m2 >> 9) - (m1 >> 9) <= TH_I) {
                int cand[3]; int nc = 2;
                cand[0] = id; cand[1] = (int)(m2 & 511u);
                if ((m3 >> 9) - (m1 >> 9) <= TH_I) cand[nc++] = (int)(m3 & 511u);
                const float* zrow = z + (gbase + tid)*DDIM;
                double bestd = 1e300; int bestk = id;
                for (int c = 0; c < nc; c++) {
                    const int k = cand[c];
                    double dd = 0.0;
                    for (int d = 0; d < DDIM; d++) {
                        double df = (double)zrow[d] - (double)E[d*KC + k];
                        dd += df*df;
                    }
                    if (dd < bestd || (dd == bestd && k < bestk)) { bestd = dd; bestk = k; }
                }
                id = bestk;
            }
            sId[tid] = id;
            g_idx[gbase + tid] = id;
            atomicAdd(&sHist[id], 1);
        }
        __syncthreads();

        // ---- quantized (Ehi+Elo) + loss; 2 threads per point, coalesced ----
        {
            const int p = tid >> 1, h = tid & 1;
            const int id = sId[p];
            const float4* zr = (const float4*)(z + (gbase + p)*DDIM + h*32);
            float4* qr = (float4*)(outq + (gbase + p)*DDIM + h*32);
            float ls = 0.f;
            #pragma unroll
            for (int j = 0; j < 8; j++) {
                int d = h*32 + j*4;
                unsigned byte = SW((unsigned)(id*128 + d*2));
                uint2 hb = *(const uint2*)((const char*)(sm + B_HI) + byte);
                uint2 lb = *(const uint2*)((const char*)(sm + B_LO) + byte);
                __nv_bfloat162 h0 = *(__nv_bfloat162*)&hb.x, h1 = *(__nv_bfloat162*)&hb.y;
                __nv_bfloat162 l0 = *(__nv_bfloat162*)&lb.x, l1 = *(__nv_bfloat162*)&lb.y;
                float q0 = __low2float(h0)  + __low2float(l0);
                float q1 = __high2float(h0) + __high2float(l0);
                float q2 = __low2float(h1)  + __low2float(l1);
                float q3 = __high2float(h1) + __high2float(l1);
                float4 zv = zr[j];
                float t0 = q0 - zv.x, t1 = q1 - zv.y, t2 = q2 - zv.z, t3 = q3 - zv.w;
                ls = fmaf(t0, t0, fmaf(t1, t1, fmaf(t2, t2, fmaf(t3, t3, ls))));
                qr[j] = make_float4(q0, q1, q2, q3);
            }
            #pragma unroll
            for (int o = 16; o; o >>= 1) ls += __shfl_down_sync(0xffffffffu, ls, o);
            if (lane == 0) sRed[w] = ls;
        }
        // flush per-tile histogram
        for (int i = tid; i < KC; i += NTHR) g_bh[t*KC + i] = sHist[i];
        __syncthreads();
        if (tid == 0) {
            float s = 0.f;
            #pragma unroll
            for (int q = 0; q < 8; q++) s += sRed[q];
            ctaLoss += s;
        }
        // next-tile smem writes are safe: all reads of this tile's arrays precede the sync above
    }
    if (tid == 0) atomicAdd(&g_losssum, ctaLoss);
}

// ---------------- K2a1: per-code scan over tiles ----------------
__global__ void __launch_bounds__(128) k2a1() {
    __shared__ int part[128];
    const int k = blockIdx.x;
    const int tid = threadIdx.x;
    int v[8]; int s = 0;
    const int t0 = tid * 8;
    #pragma unroll
    for (int j = 0; j < 8; j++) { v[j] = g_bh[(t0 + j)*KC + k]; s += v[j]; }
    part[tid] = s;
    __syncthreads();
    for (int o = 1; o < 128; o <<= 1) {
        int add = (tid >= o) ? part[tid - o] : 0;
        __syncthreads();
        part[tid] += add;
        __syncthreads();
    }
    int run = part[tid] - s;   // exclusive base
    #pragma unroll
    for (int j = 0; j < 8; j++) { g_toff[(t0 + j)*KC + k] = run; run += v[j]; }
    if (tid == 127) g_icounts[k] = part[127];
}

// ---------------- K2a2: exclusive scan over codes ----------------
__global__ void __launch_bounds__(512) k2a2() {
    __shared__ int s[KC];
    const int t = threadIdx.x;
    int c = g_icounts[t];
    s[t] = c;
    __syncthreads();
    for (int o = 1; o < KC; o <<= 1) {
        int add = (t >= o) ? s[t - o] : 0;
        __syncthreads();
        s[t] += add;
        __syncthreads();
    }
    g_start[t] = s[t] - c;
}

// ---------------- K2b: contention-free scatter ----------------
__global__ void __launch_bounds__(128) k2b() {
    __shared__ int cur[KC];
    const int t = blockIdx.x, tid = threadIdx.x;
    for (int i = tid; i < KC; i += 128) cur[i] = 0;
    __syncthreads();
    const int p = t*128 + tid;
    const int id = g_idx[p];
    const int loc = atomicAdd(&cur[id], 1);
    g_order[g_start[id] + g_toff[t*KC + id] + loc] = p;
}

// ---------------- K2c: per-code segment sum (no atomics) ----------------
__global__ void __launch_bounds__(64) k2c(const float* __restrict__ z) {
    const int k = blockIdx.x, d = threadIdx.x;
    const int start = g_start[k], cnt = g_icounts[k];
    float acc = 0.f;
    int i = 0;
    for (; i + 4 <= cnt; i += 4) {
        int p0 = g_order[start+i],   p1 = g_order[start+i+1];
        int p2 = g_order[start+i+2], p3 = g_order[start+i+3];
        acc += z[(size_t)p0*DDIM + d] + z[(size_t)p1*DDIM + d]
             + z[(size_t)p2*DDIM + d] + z[(size_t)p3*DDIM + d];
    }
    for (; i < cnt; i++) acc += z[(size_t)g_order[start+i]*DDIM + d];
    g_embedsumT[d*KC + k] = acc;
}

// ---------------- K3a: cluster-size EMA, smoothing, loss ----------------
__global__ void __launch_bounds__(512) k3a(const float* __restrict__ cs, float* __restrict__ out) {
    __shared__ float sRed[16];
    __shared__ float sN;
    const int t = threadIdx.x;
    float ncs = cs[t]*0.99f + 0.01f*(float)g_icounts[t];
    out[(size_t)NPTS*DDIM + 1 + KC*DDIM + t] = ncs;
    float v = ncs;
    #pragma unroll
    for (int o = 16; o; o >>= 1) v += __shfl_down_sync(0xffffffffu, v, o);
    if ((t & 31) == 0) sRed[t >> 5] = v;
    __syncthreads();
    if (t < 16) {
        float wv = sRed[t];
        #pragma unroll
        for (int o = 8; o; o >>= 1) wv += __shfl_down_sync(0xffffu, wv, o);
        if (t == 0) sN = wv;
    }
    __syncthreads();
    const float n = sN;
    g_smooth[t] = (ncs + 1e-5f) / (n + (float)KC * 1e-5f) * n;
    if (t == 0) out[(size_t)NPTS*DDIM] = 0.25f * (g_losssum / (float)((size_t)NPTS * DDIM));
}

// ---------------- K3b: embed_avg EMA + new embedding ----------------
__global__ void __launch_bounds__(512) k3b(const float* __restrict__ ea, float* __restrict__ out) {
    const int d = blockIdx.x, k = threadIdx.x;
    const int i = d*KC + k;
    float* out_emb = out + (size_t)NPTS*DDIM + 1;
    float* out_nea = out_emb + KC*DDIM + KC;
    float nea = ea[i]*0.99f + 0.01f*g_embedsumT[i];
    out_nea[i] = nea;
    out_emb[i] = nea / g_smooth[k];
}

// ---------------- launch ----------------
extern "C" void kernel_launch(void* const* d_in, const int* in_sizes, int n_in,
                              void* d_out, int out_size)
{
    const float* z  = (const float*)d_in[0];
    const float* E  = (const float*)d_in[1];
    const float* cs = (const float*)d_in[2];
    const float* ea = (const float*)d_in[3];
    float* out = (float*)d_out;

    cudaFuncSetAttribute(k1_main, cudaFuncAttributeMaxDynamicSharedMemorySize, SMEMB);

    k0_prep<<<1, 512>>>(E);
    k1_main<<<GRID1, NTHR, SMEMB>>>(z, E, out);
    k2a1<<<KC, 128>>>();
    k2a2<<<1, 512>>>();
    k2b<<<NTILES, 128>>>();
    k2c<<<KC, 64>>>(z);
    k3a<<<1, 512>>>(cs, out);
    k3b<<<DDIM, 512>>>(ea, out);
}